// round 1
// baseline (speedup 1.0000x reference)
#include <cuda_runtime.h>

// KeopsDFTD3Module: all-pairs D3-BJ dispersion energy, N=8192, scalar output.
// D_ij = -s6/(d2^3 + T6) - s8/(d2^4 + T8),  T6=(a1+a2)^6+eps, T8=(a1+a2)^8+eps
// masked on d2 > eps^2 (removes diagonal). Output = sum_ij D_ij.
//
// Inputs (metadata order):
//   0: atomic_numbers int32[8192]   (unused: coefficient is 0 in reference)
//   1: positions      f32[8192*3]   row-major (N,3)
//   2: r2r4           f32[95]       (unused)
//   3: a1 f32[1]  4: a2 f32[1]  5: s6 f32[1]  6: s8 f32[1]
// Output: f32[1]

#define N_ATOMS 8192
#define TPB     256
#define IPT     4                       // i-atoms per thread
#define JCHUNK  128                     // j-atoms per block tile
#define IBLOCKS (N_ATOMS / (TPB * IPT)) // 8
#define JBLOCKS (N_ATOMS / JCHUNK)      // 64
#define NBLOCKS (IBLOCKS * JBLOCKS)     // 512

__device__ float g_partials[NBLOCKS];

__device__ __forceinline__ float frcp_approx(float x) {
    float r;
    asm("rcp.approx.ftz.f32 %0, %1;" : "=f"(r) : "f"(x));
    return r;
}

__global__ __launch_bounds__(TPB) void d3_pair_kernel(
    const float* __restrict__ pos,
    const float* __restrict__ a1p, const float* __restrict__ a2p,
    const float* __restrict__ s6p, const float* __restrict__ s8p)
{
    __shared__ float sx[JCHUNK], sy[JCHUNK], sz[JCHUNK];

    const float a1 = *a1p, a2 = *a2p;
    const float s6 = *s6p, s8 = *s8p;
    const float t  = a1 + a2;
    const float t2 = t * t;
    const float t6 = t2 * t2 * t2;
    const float t8 = t6 * t2;
    const float C6 = t6 + 1e-12f;
    const float C8 = t8 + 1e-12f;
    const float EPS2 = 1e-24f;

    // Load this block's j-tile into shared (broadcast-reused by all threads).
    const int j0 = blockIdx.y * JCHUNK;
    if (threadIdx.x < JCHUNK) {
        const int j = j0 + threadIdx.x;
        sx[threadIdx.x] = pos[3 * j + 0];
        sy[threadIdx.x] = pos[3 * j + 1];
        sz[threadIdx.x] = pos[3 * j + 2];
    }
    __syncthreads();

    // Each thread owns IPT=4 i-atoms (coalesced stride TPB).
    const int ib = blockIdx.x * (TPB * IPT) + threadIdx.x;
    const int i0 = ib;
    const int i1 = ib + TPB;
    const int i2 = ib + 2 * TPB;
    const int i3 = ib + 3 * TPB;

    const float xi0 = pos[3 * i0 + 0], yi0 = pos[3 * i0 + 1], zi0 = pos[3 * i0 + 2];
    const float xi1 = pos[3 * i1 + 0], yi1 = pos[3 * i1 + 1], zi1 = pos[3 * i1 + 2];
    const float xi2 = pos[3 * i2 + 0], yi2 = pos[3 * i2 + 1], zi2 = pos[3 * i2 + 2];
    const float xi3 = pos[3 * i3 + 0], yi3 = pos[3 * i3 + 1], zi3 = pos[3 * i3 + 2];

    float acc0 = 0.f, acc1 = 0.f, acc2 = 0.f, acc3 = 0.f;

#define PAIR(k)                                                             \
    {                                                                       \
        float dx = xi##k - xj, dy = yi##k - yj, dz = zi##k - zj;            \
        float d2 = fmaf(dx, dx, fmaf(dy, dy, dz * dz));                     \
        float d4 = d2 * d2;                                                 \
        float d6 = d4 * d2;                                                 \
        float d8 = d6 * d2;                                                 \
        float A  = d6 + C6;                                                 \
        float B  = d8 + C8;                                                 \
        float num = fmaf(s8, A, s6 * B);                                    \
        float r   = frcp_approx(A * B);                                     \
        if (d2 > EPS2) acc##k = fmaf(-num, r, acc##k);                      \
    }

#pragma unroll 2
    for (int j = 0; j < JCHUNK; ++j) {
        const float xj = sx[j], yj = sy[j], zj = sz[j];
        PAIR(0)
        PAIR(1)
        PAIR(2)
        PAIR(3)
    }
#undef PAIR

    float v = (acc0 + acc1) + (acc2 + acc3);

    // Warp tree-reduce (fixed order -> deterministic).
#pragma unroll
    for (int off = 16; off > 0; off >>= 1)
        v += __shfl_down_sync(0xFFFFFFFFu, v, off);

    __shared__ float warp_sums[TPB / 32];
    if ((threadIdx.x & 31) == 0) warp_sums[threadIdx.x >> 5] = v;
    __syncthreads();

    if (threadIdx.x < 32) {
        float w = (threadIdx.x < TPB / 32) ? warp_sums[threadIdx.x] : 0.f;
#pragma unroll
        for (int off = 4; off > 0; off >>= 1)
            w += __shfl_down_sync(0xFFFFFFFFu, w, off);
        if (threadIdx.x == 0)
            g_partials[blockIdx.y * gridDim.x + blockIdx.x] = w;
    }
}

__global__ void d3_reduce_kernel(float* __restrict__ out)
{
    // One block, 512 threads; fixed-order tree reduction -> deterministic.
    const int t = threadIdx.x;
    float v = g_partials[t];
#pragma unroll
    for (int off = 16; off > 0; off >>= 1)
        v += __shfl_down_sync(0xFFFFFFFFu, v, off);

    __shared__ float warp_sums[NBLOCKS / 32]; // 16
    if ((t & 31) == 0) warp_sums[t >> 5] = v;
    __syncthreads();

    if (t < 32) {
        float w = (t < NBLOCKS / 32) ? warp_sums[t] : 0.f;
#pragma unroll
        for (int off = 8; off > 0; off >>= 1)
            w += __shfl_down_sync(0xFFFFFFFFu, w, off);
        if (t == 0) out[0] = w;
    }
}

extern "C" void kernel_launch(void* const* d_in, const int* in_sizes, int n_in,
                              void* d_out, int out_size)
{
    (void)in_sizes; (void)n_in; (void)out_size;
    const float* pos = (const float*)d_in[1];
    const float* a1p = (const float*)d_in[3];
    const float* a2p = (const float*)d_in[4];
    const float* s6p = (const float*)d_in[5];
    const float* s8p = (const float*)d_in[6];
    float* out = (float*)d_out;

    dim3 grid(IBLOCKS, JBLOCKS);
    d3_pair_kernel<<<grid, TPB>>>(pos, a1p, a2p, s6p, s8p);
    d3_reduce_kernel<<<1, NBLOCKS>>>(out);
}

// round 2
// speedup vs baseline: 1.3733x; 1.3733x over previous
#include <cuda_runtime.h>

// KeopsDFTD3Module: all-pairs D3-BJ dispersion energy, N=8192, scalar output.
//   D_ij = -s6/(d2^3 + T6) - s8/(d2^4 + T8),  T6=(a1+a2)^6+eps, T8=(a1+a2)^8+eps
//   diagonal (d2<=eps^2) masked out. Output = sum_ij D_ij.
//
// Strategy: packed f32x2 FMAs (FFMA2), d2 via dot-product identity, single
// fused kernel with last-block reduction, diagonal corrected analytically.
//
// Inputs (metadata order):
//   0: atomic_numbers int32[8192] (unused)  1: positions f32[8192*3]
//   2: r2r4 f32[95] (unused)  3: a1  4: a2  5: s6  6: s8
// Output: f32[1]

#define N_ATOMS 8192
#define TPB     256
#define IPT     4                       // i-atoms per thread (2 packed streams)
#define JCHUNK  128
#define IBLOCKS (N_ATOMS / (TPB * IPT)) // 8
#define JBLOCKS (N_ATOMS / JCHUNK)      // 64
#define NBLOCKS (IBLOCKS * JBLOCKS)     // 512

typedef unsigned long long u64;

__device__ float        g_partials[NBLOCKS];
__device__ unsigned int g_count = 0;

__device__ __forceinline__ u64 pack2(float lo, float hi) {
    u64 d; asm("mov.b64 %0, {%1, %2};" : "=l"(d) : "f"(lo), "f"(hi)); return d;
}
__device__ __forceinline__ void unpack2(float& lo, float& hi, u64 v) {
    asm("mov.b64 {%0, %1}, %2;" : "=f"(lo), "=f"(hi) : "l"(v));
}
__device__ __forceinline__ u64 ffma2(u64 a, u64 b, u64 c) {
    u64 d; asm("fma.rn.f32x2 %0, %1, %2, %3;" : "=l"(d) : "l"(a), "l"(b), "l"(c)); return d;
}
__device__ __forceinline__ u64 fmul2(u64 a, u64 b) {
    u64 d; asm("mul.rn.f32x2 %0, %1, %2;" : "=l"(d) : "l"(a), "l"(b)); return d;
}
__device__ __forceinline__ u64 fadd2(u64 a, u64 b) {
    u64 d; asm("add.rn.f32x2 %0, %1, %2;" : "=l"(d) : "l"(a), "l"(b)); return d;
}
__device__ __forceinline__ float frcp(float x) {
    float r; asm("rcp.approx.ftz.f32 %0, %1;" : "=f"(r) : "f"(x)); return r;
}

__global__ __launch_bounds__(TPB) void d3_pair_fused(
    const float* __restrict__ pos,
    const float* __restrict__ a1p, const float* __restrict__ a2p,
    const float* __restrict__ s6p, const float* __restrict__ s8p,
    float* __restrict__ out)
{
    // j-tile in shared, duplicated halves for f32x2 broadcast:
    //   sjA[j] = { pack2(-2xj,-2xj), pack2(-2yj,-2yj) }
    //   sjB[j] = { pack2(-2zj,-2zj), pack2( nj , nj ) }
    __shared__ ulonglong2 sjA[JCHUNK];
    __shared__ ulonglong2 sjB[JCHUNK];
    __shared__ float s_wsum[TPB / 32];
    __shared__ int   s_last;

    const float a1 = *a1p, a2 = *a2p;
    const float s6 = *s6p, s8 = *s8p;
    const float t  = a1 + a2;
    const float t2 = t * t;
    const float t6 = t2 * t2 * t2;
    const float t8 = t6 * t2;
    const float C6 = t6 + 1e-12f;
    const float C8 = t8 + 1e-12f;

    const u64 C6p = pack2(C6, C6);
    const u64 C8p = pack2(C8, C8);
    const u64 s6n = pack2(-s6, -s6);   // negated -> num comes out negative
    const u64 s8n = pack2(-s8, -s8);

    const int j0 = blockIdx.y * JCHUNK;
    if (threadIdx.x < JCHUNK) {
        const int j = j0 + threadIdx.x;
        const float xj = pos[3 * j + 0];
        const float yj = pos[3 * j + 1];
        const float zj = pos[3 * j + 2];
        const float nj = fmaf(xj, xj, fmaf(yj, yj, zj * zj));
        sjA[threadIdx.x] = make_ulonglong2(pack2(-2.f * xj, -2.f * xj),
                                           pack2(-2.f * yj, -2.f * yj));
        sjB[threadIdx.x] = make_ulonglong2(pack2(-2.f * zj, -2.f * zj),
                                           pack2(nj, nj));
    }
    __syncthreads();

    const int ib = blockIdx.x * (TPB * IPT) + threadIdx.x;
    float xi[IPT], yi[IPT], zi[IPT], ni[IPT];
#pragma unroll
    for (int k = 0; k < IPT; ++k) {
        const int i = ib + k * TPB;
        xi[k] = pos[3 * i + 0];
        yi[k] = pos[3 * i + 1];
        zi[k] = pos[3 * i + 2];
        ni[k] = fmaf(xi[k], xi[k], fmaf(yi[k], yi[k], zi[k] * zi[k]));
    }

    // Two packed i-streams: A=(i0,i1), B=(i2,i3)
    const u64 xA = pack2(xi[0], xi[1]), yA = pack2(yi[0], yi[1]);
    const u64 zA = pack2(zi[0], zi[1]), nA = pack2(ni[0], ni[1]);
    const u64 xB = pack2(xi[2], xi[3]), yB = pack2(yi[2], yi[3]);
    const u64 zB = pack2(zi[2], zi[3]), nB = pack2(ni[2], ni[3]);

    u64 accA = pack2(0.f, 0.f);
    u64 accB = pack2(0.f, 0.f);

#pragma unroll 4
    for (int j = 0; j < JCHUNK; ++j) {
        const ulonglong2 ja = sjA[j];
        const ulonglong2 jb = sjB[j];
        const u64 m2x = ja.x, m2y = ja.y, m2z = jb.x, njp = jb.y;

#define STREAM(X, Y, Z, NI, ACC)                                            \
        {                                                                   \
            u64 h  = fadd2(NI, njp);                /* ni + nj          */  \
            h      = ffma2(m2z, Z, h);                                      \
            h      = ffma2(m2y, Y, h);                                      \
            u64 d2 = ffma2(m2x, X, h);              /* |ri-rj|^2        */  \
            u64 d4 = fmul2(d2, d2);                                         \
            u64 A_ = ffma2(d4, d2, C6p);            /* d^6 + T6         */  \
            u64 B_ = ffma2(d4, d4, C8p);            /* d^8 + T8         */  \
            u64 P  = fmul2(A_, B_);                                         \
            u64 nm = ffma2(s8n, A_, fmul2(s6n, B_));/* -(s6 B + s8 A)   */  \
            float pl, ph; unpack2(pl, ph, P);                               \
            const u64 r = pack2(frcp(pl), frcp(ph));                        \
            ACC = ffma2(nm, r, ACC);                                        \
        }
        STREAM(xA, yA, zA, nA, accA)
        STREAM(xB, yB, zB, nB, accB)
#undef STREAM
    }

    float a0, a1h, b0, b1h;
    unpack2(a0, a1h, accA);
    unpack2(b0, b1h, accB);
    float v = (a0 + a1h) + (b0 + b1h);

#pragma unroll
    for (int off = 16; off > 0; off >>= 1)
        v += __shfl_down_sync(0xFFFFFFFFu, v, off);
    if ((threadIdx.x & 31) == 0) s_wsum[threadIdx.x >> 5] = v;
    __syncthreads();

    if (threadIdx.x == 0) {
        float w = 0.f;
#pragma unroll
        for (int k = 0; k < TPB / 32; ++k) w += s_wsum[k];
        g_partials[blockIdx.y * gridDim.x + blockIdx.x] = w;
        __threadfence();
        const unsigned int old = atomicAdd(&g_count, 1u);
        s_last = (old == NBLOCKS - 1);
    }
    __syncthreads();

    // Last block: reduce all partials (fixed order -> deterministic),
    // add analytic diagonal correction, reset counter for graph replay.
    if (s_last) {
        const int tx = threadIdx.x;
        float v2 = g_partials[tx] + g_partials[tx + TPB];
#pragma unroll
        for (int off = 16; off > 0; off >>= 1)
            v2 += __shfl_down_sync(0xFFFFFFFFu, v2, off);
        if ((tx & 31) == 0) s_wsum[tx >> 5] = v2;
        __syncthreads();
        if (tx == 0) {
            float tot = 0.f;
#pragma unroll
            for (int k = 0; k < TPB / 32; ++k) tot += s_wsum[k];
            const float diag = (float)N_ATOMS * (s6 / C6 + s8 / C8);
            out[0] = tot + diag;
            g_count = 0;
        }
    }
}

extern "C" void kernel_launch(void* const* d_in, const int* in_sizes, int n_in,
                              void* d_out, int out_size)
{
    (void)in_sizes; (void)n_in; (void)out_size;
    const float* pos = (const float*)d_in[1];
    const float* a1p = (const float*)d_in[3];
    const float* a2p = (const float*)d_in[4];
    const float* s6p = (const float*)d_in[5];
    const float* s8p = (const float*)d_in[6];
    float* out = (float*)d_out;

    dim3 grid(IBLOCKS, JBLOCKS);
    d3_pair_fused<<<grid, TPB>>>(pos, a1p, a2p, s6p, s8p, out);
}

// round 3
// speedup vs baseline: 1.4899x; 1.0849x over previous
#include <cuda_runtime.h>

// KeopsDFTD3Module: all-pairs D3-BJ dispersion energy, N=8192, scalar output.
//   D_ij = -s6/(d2^3 + T6) - s8/(d2^4 + T8),  T6=(a1+a2)^6+eps, T8=(a1+a2)^8+eps
//   diagonal (d2<=eps^2) masked out. Output = sum_ij D_ij.
//
// R3: packed f32x2 FMAs, dot-product d2, fused last-block reduction,
// diagonal corrected analytically. TPB=128 -> 1024 small CTAs, all resident
// in one wave (~10 CTA/SM capacity at 48 regs) to double latency hiding.
//
// Inputs (metadata order):
//   0: atomic_numbers int32[8192] (unused)  1: positions f32[8192*3]
//   2: r2r4 f32[95] (unused)  3: a1  4: a2  5: s6  6: s8
// Output: f32[1]

#define N_ATOMS 8192
#define TPB     128
#define IPT     4                       // i-atoms per thread (2 packed streams)
#define JCHUNK  128
#define IBLOCKS (N_ATOMS / (TPB * IPT)) // 16
#define JBLOCKS (N_ATOMS / JCHUNK)      // 64
#define NBLOCKS (IBLOCKS * JBLOCKS)     // 1024

typedef unsigned long long u64;

__device__ float        g_partials[NBLOCKS];
__device__ unsigned int g_count = 0;

__device__ __forceinline__ u64 pack2(float lo, float hi) {
    u64 d; asm("mov.b64 %0, {%1, %2};" : "=l"(d) : "f"(lo), "f"(hi)); return d;
}
__device__ __forceinline__ void unpack2(float& lo, float& hi, u64 v) {
    asm("mov.b64 {%0, %1}, %2;" : "=f"(lo), "=f"(hi) : "l"(v));
}
__device__ __forceinline__ u64 ffma2(u64 a, u64 b, u64 c) {
    u64 d; asm("fma.rn.f32x2 %0, %1, %2, %3;" : "=l"(d) : "l"(a), "l"(b), "l"(c)); return d;
}
__device__ __forceinline__ u64 fmul2(u64 a, u64 b) {
    u64 d; asm("mul.rn.f32x2 %0, %1, %2;" : "=l"(d) : "l"(a), "l"(b)); return d;
}
__device__ __forceinline__ u64 fadd2(u64 a, u64 b) {
    u64 d; asm("add.rn.f32x2 %0, %1, %2;" : "=l"(d) : "l"(a), "l"(b)); return d;
}
__device__ __forceinline__ float frcp(float x) {
    float r; asm("rcp.approx.ftz.f32 %0, %1;" : "=f"(r) : "f"(x)); return r;
}

__global__ __launch_bounds__(TPB) void d3_pair_fused(
    const float* __restrict__ pos,
    const float* __restrict__ a1p, const float* __restrict__ a2p,
    const float* __restrict__ s6p, const float* __restrict__ s8p,
    float* __restrict__ out)
{
    // j-tile in shared, duplicated halves for f32x2 broadcast:
    //   sjA[j] = { pack2(-2xj,-2xj), pack2(-2yj,-2yj) }
    //   sjB[j] = { pack2(-2zj,-2zj), pack2( nj , nj ) }
    __shared__ ulonglong2 sjA[JCHUNK];
    __shared__ ulonglong2 sjB[JCHUNK];
    __shared__ float s_wsum[TPB / 32];
    __shared__ int   s_last;

    const float a1 = *a1p, a2 = *a2p;
    const float s6 = *s6p, s8 = *s8p;
    const float t  = a1 + a2;
    const float t2 = t * t;
    const float t6 = t2 * t2 * t2;
    const float t8 = t6 * t2;
    const float C6 = t6 + 1e-12f;
    const float C8 = t8 + 1e-12f;

    const u64 C6p = pack2(C6, C6);
    const u64 C8p = pack2(C8, C8);
    const u64 s6n = pack2(-s6, -s6);   // negated -> num comes out negative
    const u64 s8n = pack2(-s8, -s8);

    // Load this block's j-tile into shared (TPB == JCHUNK).
    {
        const int j = blockIdx.y * JCHUNK + threadIdx.x;
        const float xj = pos[3 * j + 0];
        const float yj = pos[3 * j + 1];
        const float zj = pos[3 * j + 2];
        const float nj = fmaf(xj, xj, fmaf(yj, yj, zj * zj));
        sjA[threadIdx.x] = make_ulonglong2(pack2(-2.f * xj, -2.f * xj),
                                           pack2(-2.f * yj, -2.f * yj));
        sjB[threadIdx.x] = make_ulonglong2(pack2(-2.f * zj, -2.f * zj),
                                           pack2(nj, nj));
    }
    __syncthreads();

    const int ib = blockIdx.x * (TPB * IPT) + threadIdx.x;
    float xi[IPT], yi[IPT], zi[IPT], ni[IPT];
#pragma unroll
    for (int k = 0; k < IPT; ++k) {
        const int i = ib + k * TPB;
        xi[k] = pos[3 * i + 0];
        yi[k] = pos[3 * i + 1];
        zi[k] = pos[3 * i + 2];
        ni[k] = fmaf(xi[k], xi[k], fmaf(yi[k], yi[k], zi[k] * zi[k]));
    }

    // Two packed i-streams: A=(i0,i1), B=(i2,i3)
    const u64 xA = pack2(xi[0], xi[1]), yA = pack2(yi[0], yi[1]);
    const u64 zA = pack2(zi[0], zi[1]), nA = pack2(ni[0], ni[1]);
    const u64 xB = pack2(xi[2], xi[3]), yB = pack2(yi[2], yi[3]);
    const u64 zB = pack2(zi[2], zi[3]), nB = pack2(ni[2], ni[3]);

    u64 accA = pack2(0.f, 0.f);
    u64 accB = pack2(0.f, 0.f);

#pragma unroll 4
    for (int j = 0; j < JCHUNK; ++j) {
        const ulonglong2 ja = sjA[j];
        const ulonglong2 jb = sjB[j];
        const u64 m2x = ja.x, m2y = ja.y, m2z = jb.x, njp = jb.y;

#define STREAM(X, Y, Z, NI, ACC)                                            \
        {                                                                   \
            u64 h  = fadd2(NI, njp);                /* ni + nj          */  \
            h      = ffma2(m2z, Z, h);                                      \
            h      = ffma2(m2y, Y, h);                                      \
            u64 d2 = ffma2(m2x, X, h);              /* |ri-rj|^2        */  \
            u64 d4 = fmul2(d2, d2);                                         \
            u64 A_ = ffma2(d4, d2, C6p);            /* d^6 + T6         */  \
            u64 B_ = ffma2(d4, d4, C8p);            /* d^8 + T8         */  \
            u64 P  = fmul2(A_, B_);                                         \
            u64 nm = ffma2(s8n, A_, fmul2(s6n, B_));/* -(s6 B + s8 A)   */  \
            float pl, ph; unpack2(pl, ph, P);                               \
            const u64 r = pack2(frcp(pl), frcp(ph));                        \
            ACC = ffma2(nm, r, ACC);                                        \
        }
        STREAM(xA, yA, zA, nA, accA)
        STREAM(xB, yB, zB, nB, accB)
#undef STREAM
    }

    float a0, a1h, b0, b1h;
    unpack2(a0, a1h, accA);
    unpack2(b0, b1h, accB);
    float v = (a0 + a1h) + (b0 + b1h);

#pragma unroll
    for (int off = 16; off > 0; off >>= 1)
        v += __shfl_down_sync(0xFFFFFFFFu, v, off);
    if ((threadIdx.x & 31) == 0) s_wsum[threadIdx.x >> 5] = v;
    __syncthreads();

    if (threadIdx.x == 0) {
        float w = 0.f;
#pragma unroll
        for (int k = 0; k < TPB / 32; ++k) w += s_wsum[k];
        g_partials[blockIdx.y * gridDim.x + blockIdx.x] = w;
        __threadfence();
        const unsigned int old = atomicAdd(&g_count, 1u);
        s_last = (old == NBLOCKS - 1);
    }
    __syncthreads();

    // Last block: reduce all partials (fixed order -> deterministic),
    // add analytic diagonal correction, reset counter for graph replay.
    if (s_last) {
        __threadfence();
        const int tx = threadIdx.x;
        float v2 = 0.f;
#pragma unroll
        for (int k = 0; k < NBLOCKS / TPB; ++k)      // 8 values each
            v2 += g_partials[tx + k * TPB];
#pragma unroll
        for (int off = 16; off > 0; off >>= 1)
            v2 += __shfl_down_sync(0xFFFFFFFFu, v2, off);
        if ((tx & 31) == 0) s_wsum[tx >> 5] = v2;
        __syncthreads();
        if (tx == 0) {
            float tot = 0.f;
#pragma unroll
            for (int k = 0; k < TPB / 32; ++k) tot += s_wsum[k];
            const float diag = (float)N_ATOMS * (s6 / C6 + s8 / C8);
            out[0] = tot + diag;
            g_count = 0;
        }
    }
}

extern "C" void kernel_launch(void* const* d_in, const int* in_sizes, int n_in,
                              void* d_out, int out_size)
{
    (void)in_sizes; (void)n_in; (void)out_size;
    const float* pos = (const float*)d_in[1];
    const float* a1p = (const float*)d_in[3];
    const float* a2p = (const float*)d_in[4];
    const float* s6p = (const float*)d_in[5];
    const float* s8p = (const float*)d_in[6];
    float* out = (float*)d_out;

    dim3 grid(IBLOCKS, JBLOCKS);
    d3_pair_fused<<<grid, TPB>>>(pos, a1p, a2p, s6p, s8p, out);
}

// round 6
// speedup vs baseline: 1.9067x; 1.2798x over previous
#include <cuda_runtime.h>

// KeopsDFTD3Module: all-pairs D3-BJ dispersion energy, N=8192, scalar output.
//   D_ij = -s6/(d2^3 + T6) - s8/(d2^4 + T8),  T6=(a1+a2)^6+eps, T8=(a1+a2)^8+eps
//   diagonal masked out. Output = sum_ij D_ij.
//
// R4: exploit exact (bitwise) i<->j symmetry of the summand.
//   d2 = ni + nj - 2 xi.xj  (commutative, identical rounding both orders)
//   => S(tileA,tileB) == S(tileB,tileA) exactly. Compute upper-triangle tile
//   pairs only: 32 tiles of 256 atoms, 528 unordered pairs (0.516x pair work),
//   off-diagonal pairs weighted 2, diagonal tiles weight 1 (self-pairs removed
//   analytically). Packed f32x2 FMAs throughout; fused last-block reduction.
//
// Inputs (metadata order):
//   0: atomic_numbers int32[8192] (unused)  1: positions f32[8192*3]
//   2: r2r4 f32[95] (unused)  3: a1  4: a2  5: s6  6: s8
// Output: f32[1]

#define N_ATOMS  8192
#define TPB      128
#define TILE     256                    // atoms per symmetric tile
#define NTILES   (N_ATOMS / TILE)       // 32
#define NPAIRS   (NTILES * (NTILES + 1) / 2) // 528
#define JSPLIT   4                      // j-chunks per tile pair
#define JCHUNK   (TILE / JSPLIT)        // 64
#define NBLOCKS  (NPAIRS * JSPLIT)      // 2112

typedef unsigned long long u64;

__device__ float        g_partials[NBLOCKS];
__device__ unsigned int g_count = 0;

__device__ __forceinline__ u64 pack2(float lo, float hi) {
    u64 d; asm("mov.b64 %0, {%1, %2};" : "=l"(d) : "f"(lo), "f"(hi)); return d;
}
__device__ __forceinline__ void unpack2(float& lo, float& hi, u64 v) {
    asm("mov.b64 {%0, %1}, %2;" : "=f"(lo), "=f"(hi) : "l"(v));
}
__device__ __forceinline__ u64 ffma2(u64 a, u64 b, u64 c) {
    u64 d; asm("fma.rn.f32x2 %0, %1, %2, %3;" : "=l"(d) : "l"(a), "l"(b), "l"(c)); return d;
}
__device__ __forceinline__ u64 fmul2(u64 a, u64 b) {
    u64 d; asm("mul.rn.f32x2 %0, %1, %2;" : "=l"(d) : "l"(a), "l"(b)); return d;
}
__device__ __forceinline__ u64 fadd2(u64 a, u64 b) {
    u64 d; asm("add.rn.f32x2 %0, %1, %2;" : "=l"(d) : "l"(a), "l"(b)); return d;
}
__device__ __forceinline__ float frcp(float x) {
    float r; asm("rcp.approx.ftz.f32 %0, %1;" : "=f"(r) : "f"(x)); return r;
}

__global__ __launch_bounds__(TPB) void d3_pair_tri(
    const float* __restrict__ pos,
    const float* __restrict__ a1p, const float* __restrict__ a2p,
    const float* __restrict__ s6p, const float* __restrict__ s8p,
    float* __restrict__ out)
{
    // j-chunk in shared, lane-duplicated for f32x2 broadcast:
    //   sjA[j] = { (-2xj,-2xj), (-2yj,-2yj) },  sjB[j] = { (-2zj,-2zj), (nj,nj) }
    __shared__ ulonglong2 sjA[JCHUNK];
    __shared__ ulonglong2 sjB[JCHUNK];
    __shared__ float s_wsum[TPB / 32];
    __shared__ int   s_last;

    const float a1 = *a1p, a2 = *a2p;
    const float s6 = *s6p, s8 = *s8p;
    const float t  = a1 + a2;
    const float t2 = t * t;
    const float t6 = t2 * t2 * t2;
    const float t8 = t6 * t2;
    const float C6 = t6 + 1e-12f;
    const float C8 = t8 + 1e-12f;

    const u64 C6p = pack2(C6, C6);
    const u64 C8p = pack2(C8, C8);
    const u64 s6n = pack2(-s6, -s6);
    const u64 s8n = pack2(-s8, -s8);

    // Decode block -> (tile_i, tile_j, j-chunk), upper triangle ti <= tj.
    int p  = blockIdx.x >> 2;        // unordered tile-pair index [0,528)
    const int jh = blockIdx.x & 3;   // j-chunk within the tile pair
    int ti = 0;
    while (p >= NTILES - ti) { p -= NTILES - ti; ++ti; }
    const int tj = ti + p;
    const float w = (ti == tj) ? 1.0f : 2.0f;

    // Load j-chunk into shared (first JCHUNK threads).
    const int j0 = tj * TILE + jh * JCHUNK;
    if (threadIdx.x < JCHUNK) {
        const int j = j0 + threadIdx.x;
        const float xj = pos[3 * j + 0];
        const float yj = pos[3 * j + 1];
        const float zj = pos[3 * j + 2];
        const float nj = fmaf(xj, xj, fmaf(yj, yj, zj * zj));
        sjA[threadIdx.x] = make_ulonglong2(pack2(-2.f * xj, -2.f * xj),
                                           pack2(-2.f * yj, -2.f * yj));
        sjB[threadIdx.x] = make_ulonglong2(pack2(-2.f * zj, -2.f * zj),
                                           pack2(nj, nj));
    }
    __syncthreads();

    // This thread's two i-atoms (one packed stream): lanes (i0, i0+128).
    const int i0 = ti * TILE + threadIdx.x;
    const int i1 = i0 + TPB;
    const float x0 = pos[3 * i0 + 0], y0 = pos[3 * i0 + 1], z0 = pos[3 * i0 + 2];
    const float x1 = pos[3 * i1 + 0], y1 = pos[3 * i1 + 1], z1 = pos[3 * i1 + 2];
    const float n0 = fmaf(x0, x0, fmaf(y0, y0, z0 * z0));
    const float n1 = fmaf(x1, x1, fmaf(y1, y1, z1 * z1));

    const u64 xA = pack2(x0, x1), yA = pack2(y0, y1);
    const u64 zA = pack2(z0, z1), nA = pack2(n0, n1);

    u64 acc = pack2(0.f, 0.f);

#pragma unroll 4
    for (int j = 0; j < JCHUNK; ++j) {
        const ulonglong2 ja = sjA[j];
        const ulonglong2 jb = sjB[j];
        u64 h  = fadd2(nA, jb.y);              // ni + nj
        h      = ffma2(jb.x, zA, h);
        h      = ffma2(ja.y, yA, h);
        u64 d2 = ffma2(ja.x, xA, h);           // |ri-rj|^2
        u64 d4 = fmul2(d2, d2);
        u64 A_ = ffma2(d4, d2, C6p);           // d^6 + T6
        u64 B_ = ffma2(d4, d4, C8p);           // d^8 + T8
        u64 P  = fmul2(A_, B_);
        u64 nm = ffma2(s8n, A_, fmul2(s6n, B_)); // -(s6 B + s8 A)
        float pl, ph; unpack2(pl, ph, P);
        const u64 r = pack2(frcp(pl), frcp(ph));
        acc = ffma2(nm, r, acc);
    }

    float al, ah;
    unpack2(al, ah, acc);
    float v = (al + ah) * w;                    // tile-pair weight (1 or 2)

#pragma unroll
    for (int off = 16; off > 0; off >>= 1)
        v += __shfl_down_sync(0xFFFFFFFFu, v, off);
    if ((threadIdx.x & 31) == 0) s_wsum[threadIdx.x >> 5] = v;
    __syncthreads();

    if (threadIdx.x == 0) {
        float ws = 0.f;
#pragma unroll
        for (int k = 0; k < TPB / 32; ++k) ws += s_wsum[k];
        g_partials[blockIdx.x] = ws;
        __threadfence();
        const unsigned int old = atomicAdd(&g_count, 1u);
        s_last = (old == NBLOCKS - 1);
    }
    __syncthreads();

    // Last block: reduce all partials (fixed order -> deterministic),
    // add analytic self-pair correction, reset counter for graph replay.
    if (s_last) {
        __threadfence();
        const int tx = threadIdx.x;
        float v2 = 0.f;
        for (int idx = tx; idx < NBLOCKS; idx += TPB)
            v2 += g_partials[idx];
#pragma unroll
        for (int off = 16; off > 0; off >>= 1)
            v2 += __shfl_down_sync(0xFFFFFFFFu, v2, off);
        if ((tx & 31) == 0) s_wsum[tx >> 5] = v2;
        __syncthreads();
        if (tx == 0) {
            float tot = 0.f;
#pragma unroll
            for (int k = 0; k < TPB / 32; ++k) tot += s_wsum[k];
            const float diag = (float)N_ATOMS * (s6 / C6 + s8 / C8);
            out[0] = tot + diag;
            g_count = 0;
        }
    }
}

extern "C" void kernel_launch(void* const* d_in, const int* in_sizes, int n_in,
                              void* d_out, int out_size)
{
    (void)in_sizes; (void)n_in; (void)out_size;
    const float* pos = (const float*)d_in[1];
    const float* a1p = (const float*)d_in[3];
    const float* a2p = (const float*)d_in[4];
    const float* s6p = (const float*)d_in[5];
    const float* s8p = (const float*)d_in[6];
    float* out = (float*)d_out;

    d3_pair_tri<<<NBLOCKS, TPB>>>(pos, a1p, a2p, s6p, s8p, out);
}

// round 7
// speedup vs baseline: 2.2462x; 1.1780x over previous
#include <cuda_runtime.h>

// KeopsDFTD3Module: all-pairs D3-BJ dispersion energy, N=8192, scalar output.
//   D_ij = -s6/(d2^3 + T6) - s8/(d2^4 + T8),  T6=(a1+a2)^6+eps, T8=(a1+a2)^8+eps
//   diagonal masked out. Output = sum_ij D_ij.
//
// R7: exact-symmetry triangle (d2 = ni+nj-2ri.rj is bitwise symmetric) with
// TWO packed f32x2 i-streams per thread for ILP (the R6 single-stream version
// was dependency-chain bound: fma% fell 57->39). 16 tiles of 512 atoms,
// 136 unordered tile pairs x 8 j-chunks = 1088 identical CTAs. Off-diagonal
// pairs weighted 2; self-pairs removed analytically. Fused last-block reduce.
//
// Inputs (metadata order):
//   0: atomic_numbers int32[8192] (unused)  1: positions f32[8192*3]
//   2: r2r4 f32[95] (unused)  3: a1  4: a2  5: s6  6: s8
// Output: f32[1]

#define N_ATOMS  8192
#define TPB      128
#define TILE     512                    // atoms per symmetric tile
#define NTILES   (N_ATOMS / TILE)       // 16
#define NPAIRS   (NTILES * (NTILES + 1) / 2) // 136
#define JSPLIT   8                      // j-chunks per tile pair
#define JCHUNK   (TILE / JSPLIT)        // 64
#define NBLOCKS  (NPAIRS * JSPLIT)      // 1088

typedef unsigned long long u64;

__device__ float        g_partials[NBLOCKS];
__device__ unsigned int g_count = 0;

__device__ __forceinline__ u64 pack2(float lo, float hi) {
    u64 d; asm("mov.b64 %0, {%1, %2};" : "=l"(d) : "f"(lo), "f"(hi)); return d;
}
__device__ __forceinline__ void unpack2(float& lo, float& hi, u64 v) {
    asm("mov.b64 {%0, %1}, %2;" : "=f"(lo), "=f"(hi) : "l"(v));
}
__device__ __forceinline__ u64 ffma2(u64 a, u64 b, u64 c) {
    u64 d; asm("fma.rn.f32x2 %0, %1, %2, %3;" : "=l"(d) : "l"(a), "l"(b), "l"(c)); return d;
}
__device__ __forceinline__ u64 fmul2(u64 a, u64 b) {
    u64 d; asm("mul.rn.f32x2 %0, %1, %2;" : "=l"(d) : "l"(a), "l"(b)); return d;
}
__device__ __forceinline__ u64 fadd2(u64 a, u64 b) {
    u64 d; asm("add.rn.f32x2 %0, %1, %2;" : "=l"(d) : "l"(a), "l"(b)); return d;
}
__device__ __forceinline__ float frcp(float x) {
    float r; asm("rcp.approx.ftz.f32 %0, %1;" : "=f"(r) : "f"(x)); return r;
}

__global__ __launch_bounds__(TPB) void d3_pair_tri2(
    const float* __restrict__ pos,
    const float* __restrict__ a1p, const float* __restrict__ a2p,
    const float* __restrict__ s6p, const float* __restrict__ s8p,
    float* __restrict__ out)
{
    // j-chunk in shared, lane-duplicated for f32x2 broadcast:
    //   sjA[j] = { (-2xj,-2xj), (-2yj,-2yj) },  sjB[j] = { (-2zj,-2zj), (nj,nj) }
    __shared__ ulonglong2 sjA[JCHUNK];
    __shared__ ulonglong2 sjB[JCHUNK];
    __shared__ float s_wsum[TPB / 32];
    __shared__ int   s_last;

    const float a1 = *a1p, a2 = *a2p;
    const float s6 = *s6p, s8 = *s8p;
    const float t  = a1 + a2;
    const float t2 = t * t;
    const float t6 = t2 * t2 * t2;
    const float t8 = t6 * t2;
    const float C6 = t6 + 1e-12f;
    const float C8 = t8 + 1e-12f;

    const u64 C6p = pack2(C6, C6);
    const u64 C8p = pack2(C8, C8);
    const u64 s6n = pack2(-s6, -s6);
    const u64 s8n = pack2(-s8, -s8);

    // Decode block -> (tile_i, tile_j, j-chunk), upper triangle ti <= tj.
    int p  = blockIdx.x >> 3;        // unordered tile-pair index [0,136)
    const int jh = blockIdx.x & 7;   // j-chunk within the tile pair
    int ti = 0;
    while (p >= NTILES - ti) { p -= NTILES - ti; ++ti; }
    const int tj = ti + p;
    const float w = (ti == tj) ? 1.0f : 2.0f;

    // Load j-chunk into shared (first JCHUNK threads).
    const int j0 = tj * TILE + jh * JCHUNK;
    if (threadIdx.x < JCHUNK) {
        const int j = j0 + threadIdx.x;
        const float xj = pos[3 * j + 0];
        const float yj = pos[3 * j + 1];
        const float zj = pos[3 * j + 2];
        const float nj = fmaf(xj, xj, fmaf(yj, yj, zj * zj));
        sjA[threadIdx.x] = make_ulonglong2(pack2(-2.f * xj, -2.f * xj),
                                           pack2(-2.f * yj, -2.f * yj));
        sjB[threadIdx.x] = make_ulonglong2(pack2(-2.f * zj, -2.f * zj),
                                           pack2(nj, nj));
    }
    __syncthreads();

    // Four i-atoms per thread -> two independent packed streams.
    const int ibase = ti * TILE + threadIdx.x;
    float xi[4], yi[4], zi[4], ni[4];
#pragma unroll
    for (int k = 0; k < 4; ++k) {
        const int i = ibase + k * TPB;
        xi[k] = pos[3 * i + 0];
        yi[k] = pos[3 * i + 1];
        zi[k] = pos[3 * i + 2];
        ni[k] = fmaf(xi[k], xi[k], fmaf(yi[k], yi[k], zi[k] * zi[k]));
    }
    const u64 xA = pack2(xi[0], xi[1]), yA = pack2(yi[0], yi[1]);
    const u64 zA = pack2(zi[0], zi[1]), nA = pack2(ni[0], ni[1]);
    const u64 xB = pack2(xi[2], xi[3]), yB = pack2(yi[2], yi[3]);
    const u64 zB = pack2(zi[2], zi[3]), nB = pack2(ni[2], ni[3]);

    u64 accA = pack2(0.f, 0.f);
    u64 accB = pack2(0.f, 0.f);

#pragma unroll 4
    for (int j = 0; j < JCHUNK; ++j) {
        const ulonglong2 ja = sjA[j];
        const ulonglong2 jb = sjB[j];
        const u64 m2x = ja.x, m2y = ja.y, m2z = jb.x, njp = jb.y;

#define STREAM(X, Y, Z, NI, ACC)                                            \
        {                                                                   \
            u64 h  = fadd2(NI, njp);                /* ni + nj          */  \
            h      = ffma2(m2z, Z, h);                                      \
            h      = ffma2(m2y, Y, h);                                      \
            u64 d2 = ffma2(m2x, X, h);              /* |ri-rj|^2        */  \
            u64 d4 = fmul2(d2, d2);                                         \
            u64 A_ = ffma2(d4, d2, C6p);            /* d^6 + T6         */  \
            u64 B_ = ffma2(d4, d4, C8p);            /* d^8 + T8         */  \
            u64 P  = fmul2(A_, B_);                                         \
            u64 nm = ffma2(s8n, A_, fmul2(s6n, B_));/* -(s6 B + s8 A)   */  \
            float pl, ph; unpack2(pl, ph, P);                               \
            const u64 r = pack2(frcp(pl), frcp(ph));                        \
            ACC = ffma2(nm, r, ACC);                                        \
        }
        STREAM(xA, yA, zA, nA, accA)
        STREAM(xB, yB, zB, nB, accB)
#undef STREAM
    }

    float a0, a1h, b0, b1h;
    unpack2(a0, a1h, accA);
    unpack2(b0, b1h, accB);
    float v = ((a0 + a1h) + (b0 + b1h)) * w;    // tile-pair weight (1 or 2)

#pragma unroll
    for (int off = 16; off > 0; off >>= 1)
        v += __shfl_down_sync(0xFFFFFFFFu, v, off);
    if ((threadIdx.x & 31) == 0) s_wsum[threadIdx.x >> 5] = v;
    __syncthreads();

    if (threadIdx.x == 0) {
        float ws = 0.f;
#pragma unroll
        for (int k = 0; k < TPB / 32; ++k) ws += s_wsum[k];
        g_partials[blockIdx.x] = ws;
        __threadfence();
        const unsigned int old = atomicAdd(&g_count, 1u);
        s_last = (old == NBLOCKS - 1);
    }
    __syncthreads();

    // Last block: reduce all partials (fixed order -> deterministic),
    // add analytic self-pair correction, reset counter for graph replay.
    if (s_last) {
        __threadfence();
        const int tx = threadIdx.x;
        float v2 = 0.f;
        for (int idx = tx; idx < NBLOCKS; idx += TPB)
            v2 += g_partials[idx];
#pragma unroll
        for (int off = 16; off > 0; off >>= 1)
            v2 += __shfl_down_sync(0xFFFFFFFFu, v2, off);
        if ((tx & 31) == 0) s_wsum[tx >> 5] = v2;
        __syncthreads();
        if (tx == 0) {
            float tot = 0.f;
#pragma unroll
            for (int k = 0; k < TPB / 32; ++k) tot += s_wsum[k];
            const float diag = (float)N_ATOMS * (s6 / C6 + s8 / C8);
            out[0] = tot + diag;
            g_count = 0;
        }
    }
}

extern "C" void kernel_launch(void* const* d_in, const int* in_sizes, int n_in,
                              void* d_out, int out_size)
{
    (void)in_sizes; (void)n_in; (void)out_size;
    const float* pos = (const float*)d_in[1];
    const float* a1p = (const float*)d_in[3];
    const float* a2p = (const float*)d_in[4];
    const float* s6p = (const float*)d_in[5];
    const float* s8p = (const float*)d_in[6];
    float* out = (float*)d_out;

    d3_pair_tri2<<<NBLOCKS, TPB>>>(pos, a1p, a2p, s6p, s8p, out);
}